// round 17
// baseline (speedup 1.0000x reference)
#include <cuda_runtime.h>

// out[b, idx] = prod_w ( bit_{19-w}(idx) ? sin(h[b,w]) : cos(h[b,w]) ),
// h = (x + params) * 0.5. Wire w maps to idx bit (19-w).
//
// Experiment: 256-bit stores (st.global.cs.v8.f32, sm_100a feature).
// Same optimum chunking (16384 CTAs = 256 hi-groups x 64 batches, 256
// threads, 16 KB/CTA) but each thread emits 2 x STG.256 instead of
// 4 x STG.128 -> halves L1tex store wavefronts per byte. L1tex has been the
// highest-utilized unit (73-76%) in every profile; this tests whether its
// wavefront rate caps DRAM drain.
// Thread t: lane = t&127, pair = t>>7. lo = 8*lane + j (j bits 0..2 ->
// wires 19,18,17; lane bits 0..6 -> wires 16..10). Stores hi-rows pair, pair+2.

#define N_WIRES 20
#define BATCH 64
#define THREADS 256

__global__ __launch_bounds__(THREADS, 8)
void qansatz_kernel(const float* __restrict__ x,
                    const float* __restrict__ params,
                    float* __restrict__ out)
{
    __shared__ float sc[N_WIRES];
    __shared__ float ss[N_WIRES];

    const int b   = blockIdx.y;          // batch
    const int bx  = blockIdx.x;          // hi_base = 4*bx, bx in [0,256)
    const int tid = threadIdx.x;

    // 1) cos/sin for this batch's 20 wires (one barrier)
    if (tid < N_WIRES) {
        float h = (x[b * N_WIRES + tid] + params[tid]) * 0.5f;
        float c, s;
        sincosf(h, &s, &c);
        sc[tid] = c;
        ss[tid] = s;
    }
    __syncthreads();

    const int lane = tid & 127;
    const int pair = tid >> 7;           // 0 or 1

    // 2) lo common: lo bits 3..9 = lane bits 0..6 -> wires 16..10.
    float lo_common = 1.0f;
    #pragma unroll
    for (int q = 3; q < 10; q++)
        lo_common *= ((lane >> (q - 3)) & 1) ? ss[19 - q] : sc[19 - q];

    // j bits 0..2 -> wires 19, 18, 17: 8 variants
    float lv[8];
    {
        float a0 = sc[19], a1 = ss[19];
        float b0 = sc[18], b1 = ss[18];
        float d0 = sc[17], d1 = ss[17];
        lv[0] = a0 * b0 * d0;  lv[1] = a1 * b0 * d0;
        lv[2] = a0 * b1 * d0;  lv[3] = a1 * b1 * d0;
        lv[4] = a0 * b0 * d1;  lv[5] = a1 * b0 * d1;
        lv[6] = a0 * b1 * d1;  lv[7] = a1 * b1 * d1;
    }

    // 3) hi common: hi = 4*bx + r; hi bits 2..9 = bx bits 0..7 -> wires 7..0.
    float hi_common = 1.0f;
    #pragma unroll
    for (int q = 2; q < 10; q++)
        hi_common *= ((bx >> (q - 2)) & 1) ? ss[9 - q] : sc[9 - q];

    // r bits 0..1 -> wires 9, 8; this thread handles r = pair and r = pair+2
    float hv[4];
    hv[0] = sc[9] * sc[8];
    hv[1] = ss[9] * sc[8];
    hv[2] = sc[9] * ss[8];
    hv[3] = ss[9] * ss[8];
    float phA = hv[pair];
    float phB = hv[pair + 2];

    float base = lo_common * hi_common;
    float c8[8];
    #pragma unroll
    for (int j = 0; j < 8; j++) c8[j] = base * lv[j];

    // 4) two 256-bit streaming stores per thread, 32B-aligned, coalesced.
    size_t off = ((size_t)b << 20) + ((size_t)bx << 12);
    float* dstA = out + off + ((size_t)pair << 10)       + 8 * lane;
    float* dstB = out + off + ((size_t)(pair + 2) << 10) + 8 * lane;

    asm volatile(
        "st.global.cs.v8.f32 [%0], {%1, %2, %3, %4, %5, %6, %7, %8};"
        :: "l"(dstA),
           "f"(phA * c8[0]), "f"(phA * c8[1]), "f"(phA * c8[2]), "f"(phA * c8[3]),
           "f"(phA * c8[4]), "f"(phA * c8[5]), "f"(phA * c8[6]), "f"(phA * c8[7])
        : "memory");
    asm volatile(
        "st.global.cs.v8.f32 [%0], {%1, %2, %3, %4, %5, %6, %7, %8};"
        :: "l"(dstB),
           "f"(phB * c8[0]), "f"(phB * c8[1]), "f"(phB * c8[2]), "f"(phB * c8[3]),
           "f"(phB * c8[4]), "f"(phB * c8[5]), "f"(phB * c8[6]), "f"(phB * c8[7])
        : "memory");
}

extern "C" void kernel_launch(void* const* d_in, const int* in_sizes, int n_in,
                              void* d_out, int out_size)
{
    const float* x      = (const float*)d_in[0];   // (64, 20)
    const float* params = (const float*)d_in[1];   // (20,)
    float* out          = (float*)d_out;           // (64, 2^20)

    dim3 grid(256, BATCH);                         // 16384 CTAs, 16 KB each
    qansatz_kernel<<<grid, THREADS>>>(x, params, out);
}